// round 6
// baseline (speedup 1.0000x reference)
#include <cuda_runtime.h>

#define NQ  6
#define NL  3
#define TPB 256
// 1 row per thread; global I/O staged through smem as float4.

__device__ __forceinline__ float sqrt_approx(float x) {
    float r; asm("sqrt.approx.f32 %0, %1;" : "=f"(r) : "f"(x)); return r;
}

__global__ void __launch_bounds__(TPB, 8)
qc_fused(const float4* __restrict__ x4, float4* __restrict__ o4,
         const float* __restrict__ rp, const float* __restrict__ ep,
         int n_rows) {
    // derived constants
    __shared__ float  sTh0[NQ];                 // rx[0][q]*0.5 (folded into entry)
    __shared__ float2 sCS[(NL - 1) * NQ];       // (cos, sin) for layers 1,2
    __shared__ float2 sTT[NL * (NQ - 1)];       // (1-t, t), t = sigmoid/2
    // staging buffers (identity layout, row stride 6 floats)
    __shared__ float bin [TPB * NQ];
    __shared__ float bout[TPB * NQ];

    int tid = threadIdx.x;
    if (tid < NL * NQ) {
        float rx = __ldg(&rp[tid * 3]) * 0.5f;
        if (tid < NQ) {
            sTh0[tid] = rx;
        } else {
            float s, c;
            __sincosf(rx, &s, &c);
            sCS[tid - NQ] = make_float2(c, s);
        }
    } else if (tid < NL * NQ + NL * (NQ - 1)) {
        int k = tid - NL * NQ;
        float t = 0.5f / (1.0f + __expf(-__ldg(&ep[k])));
        sTT[k] = make_float2(1.0f - t, t);
    }

    // ---- stage in: coalesced float4 gmem -> smem ----
    const int V4 = TPB * NQ / 4;                // float4s per block (384)
    long blk4 = (long)blockIdx.x * V4;
#pragma unroll
    for (int i = tid; i < V4; i += TPB)
        reinterpret_cast<float4*>(bin)[i] = __ldcs(x4 + blk4 + i);
    __syncthreads();

    int row = blockIdx.x * TPB + tid;
    if (row < n_rows) {
        const float PIH = 1.57079632679489662f;
        float sr[NQ], si[NQ];
        // entry + layer-0 rotation fused: state = e^{i(x*pi/2 - th0_q)}
#pragma unroll
        for (int q = 0; q < NQ; q++) {
            float ang = fmaf(bin[tid * NQ + q], PIH, -sTh0[q]);
            __sincosf(ang, &si[q], &sr[q]);     // real=cos, imag=sin
        }

#pragma unroll
        for (int l = 0; l < NL; l++) {
            if (l > 0) {
#pragma unroll
                for (int q = 0; q < NQ; q++) {
                    float2 cs = sCS[(l - 1) * NQ + q];
                    float nr = fmaf(cs.x, sr[q],  cs.y * si[q]);
                    float ni = fmaf(cs.x, si[q], -cs.y * sr[q]);
                    sr[q] = nr; si[q] = ni;
                }
            }
            float old4 = sr[4];
#pragma unroll
            for (int k = 0; k < NQ - 1; k++) {
                float2 tt = sTT[l * 5 + k];
                sr[k] = fmaf(tt.x, sr[k], tt.y * sr[k + 1]);
            }
            float2 tt = sTT[l * 5 + 4];
            sr[5] = fmaf(tt.x, sr[5], tt.y * old4);
        }

#pragma unroll
        for (int q = 0; q < NQ; q++)
            bout[tid * NQ + q] = sqrt_approx(fmaf(sr[q], sr[q], si[q] * si[q]));
    }
    __syncthreads();

    // ---- stage out: smem -> coalesced float4 gmem ----
#pragma unroll
    for (int i = tid; i < V4; i += TPB)
        __stcs(o4 + blk4 + i, reinterpret_cast<const float4*>(bout)[i]);
}

extern "C" void kernel_launch(void* const* d_in, const int* in_sizes, int n_in,
                              void* d_out, int out_size) {
    const float* x  = (const float*)d_in[0];  // (BATCH, 6) fp32
    const float* rp = (const float*)d_in[1];  // (3, 6, 3) fp32
    const float* ep = (const float*)d_in[2];  // (3, 5)    fp32
    float* out = (float*)d_out;

    int total_f = in_sizes[0];                // BATCH * 6
    int n_rows  = total_f / NQ;               // BATCH
    int blocks  = (n_rows + TPB - 1) / TPB;

    qc_fused<<<blocks, TPB>>>((const float4*)x, (float4*)out, rp, ep, n_rows);
}